// round 3
// baseline (speedup 1.0000x reference)
#include <cuda_runtime.h>
#include <cuda_bf16.h>
#include <cstdint>

#define XDIM 128
#define X3   (XDIM * XDIM * XDIM)   // 2,097,152 voxels
#define NB   16                     // batch

#define YTILES 16                   // 128 y / 8 rows-per-block
#define ZTILE  4
#define ZTILES (XDIM / ZTILE)       // 32
#define RBLOCKS (YTILES * ZTILES)   // 512 reduce blocks

// Grid in bf16, batch-minor: g_grid[v*NB + b]. 64 MiB, zero-init at load.
// INVARIANT: all-zero at entry to every kernel_launch (zero pass restores it).
__device__ __nv_bfloat16 g_grid[(size_t)X3 * NB];
// Per-reduce-block partials: [0..15] tv, [16..31] mse. Plain stores, no atomics.
__device__ float g_part[RBLOCKS][32];

// ---------------------------------------------------------------------------
// Scatter: one thread per index; 2 x red.global.add.v4.bf16x2 (16 batches).
// ---------------------------------------------------------------------------
__global__ void scatter_kernel(const int* __restrict__ idx,
                               const float* __restrict__ vals, int N) {
    int n = blockIdx.x * blockDim.x + threadIdx.x;
    if (n >= N) return;
    int z = idx[3 * n + 0];
    int y = idx[3 * n + 1];
    int x = idx[3 * n + 2];
    size_t v = (size_t)((z * XDIM + y) * XDIM + x);

    unsigned w[8];
#pragma unroll
    for (int g = 0; g < 8; g++) {
        float a = vals[(size_t)(2 * g) * N + n];
        float b = vals[(size_t)(2 * g + 1) * N + n];
        __nv_bfloat162 p = __floats2bfloat162_rn(a, b);  // .x=a(lo), .y=b(hi)
        w[g] = *reinterpret_cast<unsigned*>(&p);
    }

    __nv_bfloat16* base = g_grid + v * NB;
    asm volatile("red.global.add.noftz.v4.bf16x2 [%0], {%1, %2, %3, %4};"
                 :: "l"(base), "r"(w[0]), "r"(w[1]), "r"(w[2]), "r"(w[3])
                 : "memory");
    asm volatile("red.global.add.noftz.v4.bf16x2 [%0], {%1, %2, %3, %4};"
                 :: "l"(base + 8), "r"(w[4]), "r"(w[5]), "r"(w[6]), "r"(w[7])
                 : "memory");
}

// ---------------------------------------------------------------------------
// Per-word diff accumulate: d = nb - self in packed bf16x2 (1 HADD2),
// unpack via shl/and (bf16 is the top half of f32), TV via FADD with free |.|,
// MSE via packed fma.rn.f32x2.
// ---------------------------------------------------------------------------
#define ACCW(sw, nw, k, mp) do {                                              \
    __nv_bfloat162 _a = *reinterpret_cast<const __nv_bfloat162*>(&(nw));      \
    __nv_bfloat162 _b = *reinterpret_cast<const __nv_bfloat162*>(&(sw));      \
    __nv_bfloat162 _d = __hsub2(_a, _b);                                      \
    unsigned _du = *reinterpret_cast<unsigned*>(&_d);                         \
    float _lo = __uint_as_float(_du << 16);                                   \
    float _hi = __uint_as_float(_du & 0xffff0000u);                           \
    tv[(k)]     += fabsf(_lo);                                                \
    tv[(k) + 1] += fabsf(_hi);                                                \
    unsigned long long _dp;                                                   \
    asm("mov.b64 %0, {%1, %2};" : "=l"(_dp)                                   \
        : "r"(__float_as_uint(_lo)), "r"(__float_as_uint(_hi)));              \
    asm("fma.rn.f32x2 %0, %1, %2, %3;" : "=l"(mp)                             \
        : "l"(_dp), "l"(_dp), "l"(mp));                                       \
} while (0)

#define ACC4(s, nb) do {                                                      \
    ACCW((s).x, (nb).x, 0, msep[0]);                                          \
    ACCW((s).y, (nb).y, 2, msep[1]);                                          \
    ACCW((s).z, (nb).z, 4, msep[2]);                                          \
    ACCW((s).w, (nb).w, 6, msep[3]);                                          \
} while (0)

// ---------------------------------------------------------------------------
// Reduce: warp covers one (y,z) row; lane = (xl 0..15, bg 0..1); uint4 load =
// 8 batches of one voxel. Warp load = 512B contiguous (4 lines). x-diff via
// shfl_down(2); chunk-boundary lane loads x+1 directly (L1 hit). Block = 8
// warps (8 consecutive y) looping 4 z-planes: y+1 and z+1 mostly L1/L2 hits.
// ---------------------------------------------------------------------------
__global__ void reduce_kernel() {
    const uint4* __restrict__ g4 = (const uint4*)g_grid;
    int tid  = threadIdx.x;
    int lane = tid & 31;
    int wrp  = tid >> 5;             // 0..7
    int bg   = lane & 1;             // which uint4 of the voxel row
    int xl   = lane >> 1;            // 0..15
    int y    = blockIdx.x * 8 + wrp; // 0..127
    bool yok = (y < XDIM - 1);

    float tv[8];
    unsigned long long msep[4];
#pragma unroll
    for (int i = 0; i < 8; i++) tv[i] = 0.f;
#pragma unroll
    for (int i = 0; i < 4; i++) msep[i] = 0ull;

    for (int zi = 0; zi < ZTILE; zi++) {
        int z = blockIdx.y * ZTILE + zi;
        bool zok = (z < XDIM - 1);
        size_t vrow = ((size_t)z * XDIM + y) * XDIM;

#pragma unroll
        for (int c = 0; c < 8; c++) {
            int x = c * 16 + xl;
            size_t i0 = (vrow + x) * 2 + bg;
            uint4 s = g4[i0];

            // x-neighbor: shfl from lane+2 (same bg, next x); last lane loads.
            uint4 nx;
            nx.x = __shfl_down_sync(0xffffffffu, s.x, 2);
            nx.y = __shfl_down_sync(0xffffffffu, s.y, 2);
            nx.z = __shfl_down_sync(0xffffffffu, s.z, 2);
            nx.w = __shfl_down_sync(0xffffffffu, s.w, 2);
            if (xl == 15 && x < XDIM - 1) nx = g4[i0 + 2];
            if (x < XDIM - 1) { ACC4(s, nx); }

            if (yok) { uint4 ny = g4[i0 + 2 * XDIM];        ACC4(s, ny); }
            if (zok) { uint4 nz = g4[i0 + 2 * XDIM * XDIM]; ACC4(s, nz); }
        }
    }

    // Unpack packed mse pairs.
    float mse[8];
#pragma unroll
    for (int i = 0; i < 4; i++) {
        unsigned _lo, _hi;
        asm("mov.b64 {%0, %1}, %2;" : "=r"(_lo), "=r"(_hi) : "l"(msep[i]));
        mse[2 * i]     = __uint_as_float(_lo);
        mse[2 * i + 1] = __uint_as_float(_hi);
    }

    // Warp reduce over lanes sharing bg (stride-2 lanes): xor 2,4,8,16.
#pragma unroll
    for (int off = 2; off <= 16; off <<= 1) {
#pragma unroll
        for (int i = 0; i < 8; i++) {
            tv[i]  += __shfl_xor_sync(0xffffffffu, tv[i],  off);
            mse[i] += __shfl_xor_sync(0xffffffffu, mse[i], off);
        }
    }

    __shared__ float s_tv[NB], s_mse[NB];
    if (tid < NB) { s_tv[tid] = 0.f; s_mse[tid] = 0.f; }
    __syncthreads();

    if (lane < 2) {                  // lane == bg holds the warp totals
#pragma unroll
        for (int i = 0; i < 8; i++) {
            atomicAdd(&s_tv[bg * 8 + i],  tv[i]);
            atomicAdd(&s_mse[bg * 8 + i], mse[i]);
        }
    }
    __syncthreads();

    if (tid < 32) {
        int bid = blockIdx.y * gridDim.x + blockIdx.x;
        g_part[bid][tid] = (tid < 16) ? s_tv[tid] : s_mse[tid - 16];
    }
}

// ---------------------------------------------------------------------------
// Zero the touched voxels + fused finalize (last block sums g_part).
// ---------------------------------------------------------------------------
__global__ void zero_fin_kernel(const int* __restrict__ idx, int N,
                                float* __restrict__ out) {
    if (blockIdx.x == gridDim.x - 1) {
        int t = threadIdx.x;
        if (t < 32) {
            double acc = 0.0;
#pragma unroll 8
            for (int b = 0; b < RBLOCKS; b++) acc += (double)g_part[b][t];
            double norm = (t < NB) ? (double)X3
                                   : (double)(2 * XDIM * XDIM - 2 * XDIM);
            out[t] = (float)(acc / norm);
        }
        return;
    }
    int n = blockIdx.x * blockDim.x + threadIdx.x;
    if (n >= N) return;
    int z = idx[3 * n + 0];
    int y = idx[3 * n + 1];
    int x = idx[3 * n + 2];
    uint4* p = (uint4*)(g_grid + (size_t)((z * XDIM + y) * XDIM + x) * NB);
    uint4 z4 = make_uint4(0u, 0u, 0u, 0u);
    p[0] = z4;
    p[1] = z4;
}

extern "C" void kernel_launch(void* const* d_in, const int* in_sizes, int n_in,
                              void* d_out, int out_size) {
    const int*   indices = (const int*)d_in[0];
    const float* values  = (const float*)d_in[1];
    int N = in_sizes[0] / 3;        // 500000

    scatter_kernel<<<(N + 255) / 256, 256>>>(indices, values, N);
    reduce_kernel<<<dim3(YTILES, ZTILES), 256>>>();
    zero_fin_kernel<<<(N + 255) / 256 + 1, 256>>>(indices, N, (float*)d_out);
}

// round 4
// speedup vs baseline: 1.9301x; 1.9301x over previous
#include <cuda_runtime.h>
#include <cuda_bf16.h>
#include <cstdint>

#define XDIM 128
#define X3   (XDIM * XDIM * XDIM)   // 2,097,152 voxels
#define NB   16                     // batch

// Grid in bf16, batch-minor: g_grid[v*NB + b]. 64 MiB, zero-init at load.
// INVARIANT: all-zero at entry to every kernel_launch (zero pass restores it).
__device__ __nv_bfloat16 g_grid[(size_t)X3 * NB];
__device__ double g_acc[2 * NB];   // [0..15] tv sums, [16..31] mse sums

// ---------------------------------------------------------------------------
// Scatter: one thread per index; 2 x red.global.add.v4.bf16x2 (16 batches).
// ---------------------------------------------------------------------------
__global__ void scatter_kernel(const int* __restrict__ idx,
                               const float* __restrict__ vals, int N) {
    int n = blockIdx.x * blockDim.x + threadIdx.x;
    if (n >= N) return;
    int z = idx[3 * n + 0];
    int y = idx[3 * n + 1];
    int x = idx[3 * n + 2];
    size_t v = (size_t)((z * XDIM + y) * XDIM + x);

    unsigned w[8];
#pragma unroll
    for (int g = 0; g < 8; g++) {
        float a = vals[(size_t)(2 * g) * N + n];
        float b = vals[(size_t)(2 * g + 1) * N + n];
        __nv_bfloat162 p = __floats2bfloat162_rn(a, b);
        w[g] = *reinterpret_cast<unsigned*>(&p);
    }

    __nv_bfloat16* base = g_grid + v * NB;
    asm volatile("red.global.add.noftz.v4.bf16x2 [%0], {%1, %2, %3, %4};"
                 :: "l"(base), "r"(w[0]), "r"(w[1]), "r"(w[2]), "r"(w[3])
                 : "memory");
    asm volatile("red.global.add.noftz.v4.bf16x2 [%0], {%1, %2, %3, %4};"
                 :: "l"(base + 8), "r"(w[4]), "r"(w[5]), "r"(w[6]), "r"(w[7])
                 : "memory");
}

// ---------------------------------------------------------------------------
// Packed diff-accumulate: d = nb - self as bf16x2 (1 HADD2), unpack with
// shl/and (bf16 = top half of f32), TV via FADD |.|, MSE via fma.rn.f32x2.
// ---------------------------------------------------------------------------
#define ACCW(sw, nw, k, mp) do {                                              \
    __nv_bfloat162 _a = *reinterpret_cast<const __nv_bfloat162*>(&(nw));      \
    __nv_bfloat162 _b = *reinterpret_cast<const __nv_bfloat162*>(&(sw));      \
    __nv_bfloat162 _d = __hsub2(_a, _b);                                      \
    unsigned _du = *reinterpret_cast<unsigned*>(&_d);                         \
    float _lo = __uint_as_float(_du << 16);                                   \
    float _hi = __uint_as_float(_du & 0xffff0000u);                           \
    tv[(k)]     += fabsf(_lo);                                                \
    tv[(k) + 1] += fabsf(_hi);                                                \
    unsigned long long _dp;                                                   \
    asm("mov.b64 %0, {%1, %2};" : "=l"(_dp)                                   \
        : "r"(__float_as_uint(_lo)), "r"(__float_as_uint(_hi)));              \
    asm("fma.rn.f32x2 %0, %1, %2, %3;" : "=l"(mp)                             \
        : "l"(_dp), "l"(_dp), "l"(mp));                                       \
} while (0)

#define ACC4(s, nb) do {                                                      \
    ACCW((s).x, (nb).x, 0, msep[0]);                                          \
    ACCW((s).y, (nb).y, 2, msep[1]);                                          \
    ACCW((s).z, (nb).z, 4, msep[2]);                                          \
    ACCW((s).w, (nb).w, 6, msep[3]);                                          \
} while (0)

// ---------------------------------------------------------------------------
// Reduce: warp covers 16 consecutive x voxels (both uint4 halves): lane =
// xl*2 + bg -> warp load = 32 consecutive uint4 = 512B (4 lines). Neighbors:
// x+1 = direct load at +2 (L1-hits warp's own lines; divergence only in last
// chunk), y+1 at +256, z+1 at +32768. No shuffles. Block = 8 warps (8 y rows)
// looping 4 z planes.
// ---------------------------------------------------------------------------
__global__ void reduce_kernel() {
    const uint4* __restrict__ g4 = (const uint4*)g_grid;
    int tid  = threadIdx.x;
    int lane = tid & 31;
    int wrp  = tid >> 5;             // 0..7
    int bg   = lane & 1;
    int xl   = lane >> 1;            // 0..15
    int y    = blockIdx.x * 8 + wrp; // 0..127
    bool yok = (y < XDIM - 1);

    float tv[8];
    unsigned long long msep[4];
#pragma unroll
    for (int i = 0; i < 8; i++) tv[i] = 0.f;
#pragma unroll
    for (int i = 0; i < 4; i++) msep[i] = 0ull;

    for (int zi = 0; zi < 4; zi++) {
        int z = blockIdx.y * 4 + zi;
        bool zok = (z < XDIM - 1);
        size_t row2 = ((size_t)z * XDIM + y) * XDIM * 2;   // uint4 idx at x=0

#pragma unroll
        for (int c = 0; c < 8; c++) {
            size_t i0 = row2 + c * 32 + lane;
            uint4 s = g4[i0];

            if (c < 7) {
                uint4 nx = g4[i0 + 2];
                ACC4(s, nx);
            } else if (xl < 15) {                  // x = 112..126 only
                uint4 nx = g4[i0 + 2];
                ACC4(s, nx);
            }
            if (yok) { uint4 ny = g4[i0 + 2 * XDIM];        ACC4(s, ny); }
            if (zok) { uint4 nz = g4[i0 + 2 * XDIM * XDIM]; ACC4(s, nz); }
        }
    }

    // Unpack packed mse pairs.
    float mse[8];
#pragma unroll
    for (int i = 0; i < 4; i++) {
        unsigned _lo, _hi;
        asm("mov.b64 {%0, %1}, %2;" : "=r"(_lo), "=r"(_hi) : "l"(msep[i]));
        mse[2 * i]     = __uint_as_float(_lo);
        mse[2 * i + 1] = __uint_as_float(_hi);
    }

    // Warp reduce over lanes sharing bg (stride-2 lanes): xor 2,4,8,16.
#pragma unroll
    for (int off = 2; off <= 16; off <<= 1) {
#pragma unroll
        for (int i = 0; i < 8; i++) {
            tv[i]  += __shfl_xor_sync(0xffffffffu, tv[i],  off);
            mse[i] += __shfl_xor_sync(0xffffffffu, mse[i], off);
        }
    }

    __shared__ float s_tv[NB], s_mse[NB];
    if (tid < NB) { s_tv[tid] = 0.f; s_mse[tid] = 0.f; }
    __syncthreads();

    if (lane < 2) {                  // lane 0 = bg0 totals, lane 1 = bg1
#pragma unroll
        for (int i = 0; i < 8; i++) {
            atomicAdd(&s_tv[bg * 8 + i],  tv[i]);
            atomicAdd(&s_mse[bg * 8 + i], mse[i]);
        }
    }
    __syncthreads();

    if (tid < NB) {
        atomicAdd(&g_acc[tid],      (double)s_tv[tid]);
        atomicAdd(&g_acc[NB + tid], (double)s_mse[tid]);
    }
}

// ---------------------------------------------------------------------------
// Zero the touched voxels; last block finalizes (reads 32 doubles, resets).
// ---------------------------------------------------------------------------
__global__ void zero_fin_kernel(const int* __restrict__ idx, int N,
                                float* __restrict__ out) {
    if (blockIdx.x == gridDim.x - 1) {
        int t = threadIdx.x;
        if (t < 32) {
            double norm = (t < NB) ? (double)X3
                                   : (double)(2 * XDIM * XDIM - 2 * XDIM);
            out[t] = (float)(g_acc[t] / norm);
            g_acc[t] = 0.0;          // restore invariant for next replay
        }
        return;
    }
    int n = blockIdx.x * blockDim.x + threadIdx.x;
    if (n >= N) return;
    int z = idx[3 * n + 0];
    int y = idx[3 * n + 1];
    int x = idx[3 * n + 2];
    uint4* p = (uint4*)(g_grid + (size_t)((z * XDIM + y) * XDIM + x) * NB);
    uint4 z4 = make_uint4(0u, 0u, 0u, 0u);
    p[0] = z4;
    p[1] = z4;
}

extern "C" void kernel_launch(void* const* d_in, const int* in_sizes, int n_in,
                              void* d_out, int out_size) {
    const int*   indices = (const int*)d_in[0];
    const float* values  = (const float*)d_in[1];
    int N = in_sizes[0] / 3;        // 500000

    scatter_kernel<<<(N + 255) / 256, 256>>>(indices, values, N);
    reduce_kernel<<<dim3(16, 32), 256>>>();
    zero_fin_kernel<<<(N + 255) / 256 + 1, 256>>>(indices, N, (float*)d_out);
}

// round 5
// speedup vs baseline: 2.0441x; 1.0591x over previous
#include <cuda_runtime.h>
#include <cuda_bf16.h>
#include <cstdint>

#define XDIM 128
#define X3   (XDIM * XDIM * XDIM)   // 2,097,152 voxels
#define NB   16                     // batch

// Grid in bf16, batch-minor: g_grid[v*NB + b]. 64 MiB, zero-init at load.
// INVARIANT: all-zero at entry to every kernel_launch (zero pass restores it).
// Designed to stay L2-resident: all one-shot streams (indices, values) are
// loaded with .cs (evict-first) so they don't evict grid lines.
__device__ __nv_bfloat16 g_grid[(size_t)X3 * NB];
__device__ double g_acc[2 * NB];   // [0..15] tv sums, [16..31] mse sums

// ---------------------------------------------------------------------------
// Scatter: one thread per index; 2 x red.global.add.v4.bf16x2 (16 batches).
// Streams loaded with __ldcs to preserve grid L2 residency.
// ---------------------------------------------------------------------------
__global__ void scatter_kernel(const int* __restrict__ idx,
                               const float* __restrict__ vals, int N) {
    int n = blockIdx.x * blockDim.x + threadIdx.x;
    if (n >= N) return;
    int z = __ldcs(idx + 3 * n + 0);
    int y = __ldcs(idx + 3 * n + 1);
    int x = __ldcs(idx + 3 * n + 2);
    size_t v = (size_t)((z * XDIM + y) * XDIM + x);

    unsigned w[8];
#pragma unroll
    for (int g = 0; g < 8; g++) {
        float a = __ldcs(vals + (size_t)(2 * g) * N + n);
        float b = __ldcs(vals + (size_t)(2 * g + 1) * N + n);
        __nv_bfloat162 p = __floats2bfloat162_rn(a, b);
        w[g] = *reinterpret_cast<unsigned*>(&p);
    }

    __nv_bfloat16* base = g_grid + v * NB;
    asm volatile("red.global.add.noftz.v4.bf16x2 [%0], {%1, %2, %3, %4};"
                 :: "l"(base), "r"(w[0]), "r"(w[1]), "r"(w[2]), "r"(w[3])
                 : "memory");
    asm volatile("red.global.add.noftz.v4.bf16x2 [%0], {%1, %2, %3, %4};"
                 :: "l"(base + 8), "r"(w[4]), "r"(w[5]), "r"(w[6]), "r"(w[7])
                 : "memory");
}

// ---------------------------------------------------------------------------
// Packed diff-accumulate: d = nb - self as bf16x2 (1 HADD2), unpack with
// shl/and (bf16 = top half of f32), TV via FADD |.|, MSE via fma.rn.f32x2.
// ---------------------------------------------------------------------------
#define ACCW(sw, nw, k, mp) do {                                              \
    __nv_bfloat162 _a = *reinterpret_cast<const __nv_bfloat162*>(&(nw));      \
    __nv_bfloat162 _b = *reinterpret_cast<const __nv_bfloat162*>(&(sw));      \
    __nv_bfloat162 _d = __hsub2(_a, _b);                                      \
    unsigned _du = *reinterpret_cast<unsigned*>(&_d);                         \
    float _lo = __uint_as_float(_du << 16);                                   \
    float _hi = __uint_as_float(_du & 0xffff0000u);                           \
    tv[(k)]     += fabsf(_lo);                                                \
    tv[(k) + 1] += fabsf(_hi);                                                \
    unsigned long long _dp;                                                   \
    asm("mov.b64 %0, {%1, %2};" : "=l"(_dp)                                   \
        : "r"(__float_as_uint(_lo)), "r"(__float_as_uint(_hi)));              \
    asm("fma.rn.f32x2 %0, %1, %2, %3;" : "=l"(mp)                             \
        : "l"(_dp), "l"(_dp), "l"(mp));                                       \
} while (0)

#define ACC4(s, nb) do {                                                      \
    ACCW((s).x, (nb).x, 0, msep[0]);                                          \
    ACCW((s).y, (nb).y, 2, msep[1]);                                          \
    ACCW((s).z, (nb).z, 4, msep[2]);                                          \
    ACCW((s).w, (nb).w, 6, msep[3]);                                          \
} while (0)

// ---------------------------------------------------------------------------
// Reduce: warp covers 16 consecutive x voxels (both uint4 halves); warp load
// = 512B contiguous. x+1 = direct load at +2 (L1-hits warp's own lines),
// y+1 at +256 (reused as next warp's self), z+1 at +32768 (next zi's self).
// ---------------------------------------------------------------------------
__global__ void reduce_kernel() {
    const uint4* __restrict__ g4 = (const uint4*)g_grid;
    int tid  = threadIdx.x;
    int lane = tid & 31;
    int wrp  = tid >> 5;             // 0..7
    int bg   = lane & 1;
    int xl   = lane >> 1;            // 0..15
    int y    = blockIdx.x * 8 + wrp; // 0..127
    bool yok = (y < XDIM - 1);

    float tv[8];
    unsigned long long msep[4];
#pragma unroll
    for (int i = 0; i < 8; i++) tv[i] = 0.f;
#pragma unroll
    for (int i = 0; i < 4; i++) msep[i] = 0ull;

    for (int zi = 0; zi < 4; zi++) {
        int z = blockIdx.y * 4 + zi;
        bool zok = (z < XDIM - 1);
        size_t row2 = ((size_t)z * XDIM + y) * XDIM * 2;   // uint4 idx at x=0

#pragma unroll
        for (int c = 0; c < 8; c++) {
            size_t i0 = row2 + c * 32 + lane;
            uint4 s = g4[i0];

            if (c < 7) {
                uint4 nx = g4[i0 + 2];
                ACC4(s, nx);
            } else if (xl < 15) {                  // x = 112..126 only
                uint4 nx = g4[i0 + 2];
                ACC4(s, nx);
            }
            if (yok) { uint4 ny = g4[i0 + 2 * XDIM];        ACC4(s, ny); }
            if (zok) { uint4 nz = g4[i0 + 2 * XDIM * XDIM]; ACC4(s, nz); }
        }
    }

    // Unpack packed mse pairs.
    float mse[8];
#pragma unroll
    for (int i = 0; i < 4; i++) {
        unsigned _lo, _hi;
        asm("mov.b64 {%0, %1}, %2;" : "=r"(_lo), "=r"(_hi) : "l"(msep[i]));
        mse[2 * i]     = __uint_as_float(_lo);
        mse[2 * i + 1] = __uint_as_float(_hi);
    }

    // Warp reduce over lanes sharing bg (stride-2 lanes): xor 2,4,8,16.
#pragma unroll
    for (int off = 2; off <= 16; off <<= 1) {
#pragma unroll
        for (int i = 0; i < 8; i++) {
            tv[i]  += __shfl_xor_sync(0xffffffffu, tv[i],  off);
            mse[i] += __shfl_xor_sync(0xffffffffu, mse[i], off);
        }
    }

    __shared__ float s_tv[NB], s_mse[NB];
    if (tid < NB) { s_tv[tid] = 0.f; s_mse[tid] = 0.f; }
    __syncthreads();

    if (lane < 2) {                  // lane 0 = bg0 totals, lane 1 = bg1
#pragma unroll
        for (int i = 0; i < 8; i++) {
            atomicAdd(&s_tv[bg * 8 + i],  tv[i]);
            atomicAdd(&s_mse[bg * 8 + i], mse[i]);
        }
    }
    __syncthreads();

    if (tid < NB) {
        atomicAdd(&g_acc[tid],      (double)s_tv[tid]);
        atomicAdd(&g_acc[NB + tid], (double)s_mse[tid]);
    }
}

// ---------------------------------------------------------------------------
// Zero the touched voxels (index stream via .cs); last block finalizes.
// ---------------------------------------------------------------------------
__global__ void zero_fin_kernel(const int* __restrict__ idx, int N,
                                float* __restrict__ out) {
    if (blockIdx.x == gridDim.x - 1) {
        int t = threadIdx.x;
        if (t < 32) {
            double norm = (t < NB) ? (double)X3
                                   : (double)(2 * XDIM * XDIM - 2 * XDIM);
            out[t] = (float)(g_acc[t] / norm);
            g_acc[t] = 0.0;          // restore invariant for next replay
        }
        return;
    }
    int n = blockIdx.x * blockDim.x + threadIdx.x;
    if (n >= N) return;
    int z = __ldcs(idx + 3 * n + 0);
    int y = __ldcs(idx + 3 * n + 1);
    int x = __ldcs(idx + 3 * n + 2);
    uint4* p = (uint4*)(g_grid + (size_t)((z * XDIM + y) * XDIM + x) * NB);
    uint4 z4 = make_uint4(0u, 0u, 0u, 0u);
    p[0] = z4;
    p[1] = z4;
}

extern "C" void kernel_launch(void* const* d_in, const int* in_sizes, int n_in,
                              void* d_out, int out_size) {
    const int*   indices = (const int*)d_in[0];
    const float* values  = (const float*)d_in[1];
    int N = in_sizes[0] / 3;        // 500000

    scatter_kernel<<<(N + 255) / 256, 256>>>(indices, values, N);
    reduce_kernel<<<dim3(16, 32), 256>>>();
    zero_fin_kernel<<<(N + 255) / 256 + 1, 256>>>(indices, N, (float*)d_out);
}